// round 1
// baseline (speedup 1.0000x reference)
#include <cuda_runtime.h>
#include <math.h>

// Problem constants
#define Bsz  4
#define Lseq 2048
#define Dm   1024
#define Hn   16
#define HD   64
#define Mrows (Bsz*Lseq)   // 8192

// Scratch (device globals — no allocation allowed)
__device__ float g_q[(size_t)Mrows * Dm];
__device__ float g_k[(size_t)Mrows * Dm];
__device__ float g_v[(size_t)Mrows * Dm];
__device__ float g_t[(size_t)Mrows * Dm];   // V intermediate (A @ v)

// ---------------------------------------------------------------------------
// Generic C[M,N] = A[M,K] @ W[N,K]^T (+ bias), all row-major.
// 128x128 tile, BK=8, 256 threads, 8x8 per-thread register tile.
// M%128==0, N%128==0, K%8==0 assumed (holds for all uses here).
// ---------------------------------------------------------------------------
__global__ __launch_bounds__(256) void sgemm_xt(
    const float* __restrict__ A, const float* __restrict__ W,
    const float* __restrict__ bias, float* __restrict__ C,
    int M, int N, int K)
{
    __shared__ float As[8][128];
    __shared__ float Bs[8][128];

    const int tid = threadIdx.x;
    const float* Ab = A + (size_t)blockIdx.y * 128 * K;
    const float* Wb = W + (size_t)blockIdx.x * 128 * K;
    float* Cb = C + (size_t)blockIdx.y * 128 * N + blockIdx.x * 128;

    const int loadRow = tid >> 1;          // 0..127
    const int loadCol = (tid & 1) * 4;     // 0 or 4
    const int tr = (tid >> 4) * 8;         // 0..120
    const int tc = (tid & 15) * 8;         // 0..120

    float acc[8][8];
    #pragma unroll
    for (int i = 0; i < 8; i++)
        #pragma unroll
        for (int j = 0; j < 8; j++) acc[i][j] = 0.f;

    for (int k0 = 0; k0 < K; k0 += 8) {
        float4 av = *(const float4*)(Ab + (size_t)loadRow * K + k0 + loadCol);
        As[loadCol + 0][loadRow] = av.x;
        As[loadCol + 1][loadRow] = av.y;
        As[loadCol + 2][loadRow] = av.z;
        As[loadCol + 3][loadRow] = av.w;
        float4 wv = *(const float4*)(Wb + (size_t)loadRow * K + k0 + loadCol);
        Bs[loadCol + 0][loadRow] = wv.x;
        Bs[loadCol + 1][loadRow] = wv.y;
        Bs[loadCol + 2][loadRow] = wv.z;
        Bs[loadCol + 3][loadRow] = wv.w;
        __syncthreads();

        #pragma unroll
        for (int k = 0; k < 8; k++) {
            float ra[8], rb[8];
            float4 a0 = *(const float4*)&As[k][tr];
            float4 a1 = *(const float4*)&As[k][tr + 4];
            ra[0]=a0.x; ra[1]=a0.y; ra[2]=a0.z; ra[3]=a0.w;
            ra[4]=a1.x; ra[5]=a1.y; ra[6]=a1.z; ra[7]=a1.w;
            float4 b0 = *(const float4*)&Bs[k][tc];
            float4 b1 = *(const float4*)&Bs[k][tc + 4];
            rb[0]=b0.x; rb[1]=b0.y; rb[2]=b0.z; rb[3]=b0.w;
            rb[4]=b1.x; rb[5]=b1.y; rb[6]=b1.z; rb[7]=b1.w;
            #pragma unroll
            for (int i = 0; i < 8; i++)
                #pragma unroll
                for (int j = 0; j < 8; j++)
                    acc[i][j] = fmaf(ra[i], rb[j], acc[i][j]);
        }
        __syncthreads();
    }

    #pragma unroll
    for (int i = 0; i < 8; i++) {
        #pragma unroll
        for (int j4 = 0; j4 < 2; j4++) {
            float4 o;
            o.x = acc[i][j4*4+0]; o.y = acc[i][j4*4+1];
            o.z = acc[i][j4*4+2]; o.w = acc[i][j4*4+3];
            if (bias) {
                const float* bb = bias + blockIdx.x * 128 + tc + j4*4;
                o.x += bb[0]; o.y += bb[1]; o.z += bb[2]; o.w += bb[3];
            }
            *(float4*)(Cb + (size_t)(tr + i) * N + tc + j4*4) = o;
        }
    }
}

// ---------------------------------------------------------------------------
// scores: Aout[bh, l, s] = 0.125 * sum_d q[b,l,h,d] * k[b,s,h,d]
// block = (64 l) x (64 s) tile for one (b,h). 256 threads, 4x4 per thread.
// grid: (s_tiles=32, l_tiles=32, bh=64)
// ---------------------------------------------------------------------------
__global__ __launch_bounds__(256) void scores_kernel(
    const float* __restrict__ q, const float* __restrict__ k,
    float* __restrict__ Aout)
{
    __shared__ float Qt[64][68];   // [d][l]
    __shared__ float Kt[64][68];   // [d][s]

    const int bh = blockIdx.z;
    const int b  = bh >> 4;
    const int h  = bh & 15;
    const int l0 = blockIdx.y * 64;
    const int s0 = blockIdx.x * 64;
    const int tid = threadIdx.x;

    const float* qb = q + ((size_t)(b * Lseq + l0)) * Dm + h * HD;
    const float* kb = k + ((size_t)(b * Lseq + s0)) * Dm + h * HD;

    const int lr = tid >> 4;          // 0..15
    const int c4 = (tid & 15) * 4;    // 0..60
    #pragma unroll
    for (int i = 0; i < 4; i++) {
        int r = lr + i * 16;
        float4 qv = *(const float4*)(qb + (size_t)r * Dm + c4);
        Qt[c4+0][r] = qv.x; Qt[c4+1][r] = qv.y; Qt[c4+2][r] = qv.z; Qt[c4+3][r] = qv.w;
        float4 kv = *(const float4*)(kb + (size_t)r * Dm + c4);
        Kt[c4+0][r] = kv.x; Kt[c4+1][r] = kv.y; Kt[c4+2][r] = kv.z; Kt[c4+3][r] = kv.w;
    }
    __syncthreads();

    const int tr = (tid >> 4) * 4;
    const int tc = (tid & 15) * 4;
    float acc[4][4];
    #pragma unroll
    for (int i = 0; i < 4; i++)
        #pragma unroll
        for (int j = 0; j < 4; j++) acc[i][j] = 0.f;

    #pragma unroll
    for (int d = 0; d < 64; d++) {
        float4 a = *(const float4*)&Qt[d][tr];
        float4 v = *(const float4*)&Kt[d][tc];
        float ra[4] = {a.x, a.y, a.z, a.w};
        float rv[4] = {v.x, v.y, v.z, v.w};
        #pragma unroll
        for (int i = 0; i < 4; i++)
            #pragma unroll
            for (int j = 0; j < 4; j++)
                acc[i][j] = fmaf(ra[i], rv[j], acc[i][j]);
    }

    float* Ab = Aout + ((size_t)bh * Lseq + l0) * Lseq + s0;
    #pragma unroll
    for (int i = 0; i < 4; i++) {
        float4 o;
        o.x = acc[i][0] * 0.125f; o.y = acc[i][1] * 0.125f;
        o.z = acc[i][2] * 0.125f; o.w = acc[i][3] * 0.125f;
        *(float4*)(Ab + (size_t)(tr + i) * Lseq + tc) = o;
    }
}

// ---------------------------------------------------------------------------
// softmax over last dim (L=2048), in place. One block (256 thr) per row.
// ---------------------------------------------------------------------------
__global__ __launch_bounds__(256) void softmax_rows(float* __restrict__ Aio)
{
    __shared__ float red[8];
    __shared__ float bcast;

    float* rp = Aio + (size_t)blockIdx.x * Lseq;
    const int tid  = threadIdx.x;
    const int lane = tid & 31;
    const int wid  = tid >> 5;

    float4 v0 = *(float4*)(rp + tid * 8);
    float4 v1 = *(float4*)(rp + tid * 8 + 4);

    float m = fmaxf(fmaxf(fmaxf(v0.x, v0.y), fmaxf(v0.z, v0.w)),
                    fmaxf(fmaxf(v1.x, v1.y), fmaxf(v1.z, v1.w)));
    #pragma unroll
    for (int o = 16; o; o >>= 1) m = fmaxf(m, __shfl_xor_sync(0xffffffffu, m, o));
    if (lane == 0) red[wid] = m;
    __syncthreads();
    if (tid < 32) {
        float t = (lane < 8) ? red[lane] : -INFINITY;
        #pragma unroll
        for (int o = 4; o; o >>= 1) t = fmaxf(t, __shfl_xor_sync(0xffffffffu, t, o));
        if (lane == 0) bcast = t;
    }
    __syncthreads();
    m = bcast;
    __syncthreads();

    v0.x = __expf(v0.x - m); v0.y = __expf(v0.y - m);
    v0.z = __expf(v0.z - m); v0.w = __expf(v0.w - m);
    v1.x = __expf(v1.x - m); v1.y = __expf(v1.y - m);
    v1.z = __expf(v1.z - m); v1.w = __expf(v1.w - m);

    float s = (v0.x + v0.y) + (v0.z + v0.w) + (v1.x + v1.y) + (v1.z + v1.w);
    #pragma unroll
    for (int o = 16; o; o >>= 1) s += __shfl_xor_sync(0xffffffffu, s, o);
    if (lane == 0) red[wid] = s;
    __syncthreads();
    if (tid < 32) {
        float t = (lane < 8) ? red[lane] : 0.f;
        #pragma unroll
        for (int o = 4; o; o >>= 1) t += __shfl_xor_sync(0xffffffffu, t, o);
        if (lane == 0) bcast = t;
    }
    __syncthreads();
    const float inv = 1.0f / bcast;

    v0.x *= inv; v0.y *= inv; v0.z *= inv; v0.w *= inv;
    v1.x *= inv; v1.y *= inv; v1.z *= inv; v1.w *= inv;
    *(float4*)(rp + tid * 8)     = v0;
    *(float4*)(rp + tid * 8 + 4) = v1;
}

// ---------------------------------------------------------------------------
// AV: Vout[b, l, h*64+d] = sum_s A[bh, l, s] * v[b, s, h*64+d]
// per block: 64 l x 64 d tile for one (b,h), K loop over s in steps of 32.
// grid: (l_tiles=32, bh=64), 256 threads, 4x4 per thread.
// ---------------------------------------------------------------------------
__global__ __launch_bounds__(256) void av_kernel(
    const float* __restrict__ Amat, const float* __restrict__ v,
    float* __restrict__ Vout)
{
    __shared__ float As[32][68];   // [s][l]
    __shared__ float Vs[32][68];   // [s][d]

    const int bh = blockIdx.y;
    const int b  = bh >> 4;
    const int h  = bh & 15;
    const int l0 = blockIdx.x * 64;
    const int tid = threadIdx.x;

    const float* Arow = Amat + ((size_t)bh * Lseq + l0) * Lseq;
    const float* vb   = v + (size_t)b * Lseq * Dm + h * HD;

    const int tr = (tid >> 4) * 4;   // l
    const int tc = (tid & 15) * 4;   // d
    float acc[4][4];
    #pragma unroll
    for (int i = 0; i < 4; i++)
        #pragma unroll
        for (int j = 0; j < 4; j++) acc[i][j] = 0.f;

    const int aR  = tid >> 3;          // 0..31 (l, two iters -> 64)
    const int aC4 = (tid & 7) * 4;     // 0..28 (s)
    const int vR  = tid >> 4;          // 0..15 (s, two iters -> 32)
    const int vC4 = (tid & 15) * 4;    // 0..60 (d)

    for (int s0 = 0; s0 < Lseq; s0 += 32) {
        #pragma unroll
        for (int i = 0; i < 2; i++) {
            int r = aR + i * 32;
            float4 av = *(const float4*)(Arow + (size_t)r * Lseq + s0 + aC4);
            As[aC4+0][r] = av.x; As[aC4+1][r] = av.y;
            As[aC4+2][r] = av.z; As[aC4+3][r] = av.w;
        }
        #pragma unroll
        for (int i = 0; i < 2; i++) {
            int sr = vR + i * 16;
            float4 vv = *(const float4*)(vb + (size_t)(s0 + sr) * Dm + vC4);
            *(float4*)&Vs[sr][vC4] = vv;
        }
        __syncthreads();

        #pragma unroll
        for (int k = 0; k < 32; k++) {
            float4 a = *(const float4*)&As[k][tr];
            float4 w = *(const float4*)&Vs[k][tc];
            float ra[4] = {a.x, a.y, a.z, a.w};
            float rw[4] = {w.x, w.y, w.z, w.w};
            #pragma unroll
            for (int i = 0; i < 4; i++)
                #pragma unroll
                for (int j = 0; j < 4; j++)
                    acc[i][j] = fmaf(ra[i], rw[j], acc[i][j]);
        }
        __syncthreads();
    }

    #pragma unroll
    for (int i = 0; i < 4; i++) {
        float4 o;
        o.x = acc[i][0]; o.y = acc[i][1]; o.z = acc[i][2]; o.w = acc[i][3];
        *(float4*)(Vout + (size_t)(b * Lseq + l0 + tr + i) * Dm + h * HD + tc) = o;
    }
}

// ---------------------------------------------------------------------------
extern "C" void kernel_launch(void* const* d_in, const int* in_sizes, int n_in,
                              void* d_out, int out_size)
{
    const float* x  = (const float*)d_in[0];
    // d_in[1] = key_indices (unused by the reference)
    const float* Wq = (const float*)d_in[2];
    const float* Wk = (const float*)d_in[3];
    const float* Wv = (const float*)d_in[4];
    const float* Wo = (const float*)d_in[5];
    const float* bo = (const float*)d_in[6];

    float* outp = (float*)d_out;
    float* Aout = outp + (size_t)Mrows * Dm;   // A follows out in the output buffer

    float *q, *k, *v, *t;
    cudaGetSymbolAddress((void**)&q, g_q);
    cudaGetSymbolAddress((void**)&k, g_k);
    cudaGetSymbolAddress((void**)&v, g_v);
    cudaGetSymbolAddress((void**)&t, g_t);

    dim3 gProj(Dm / 128, Mrows / 128);   // (8, 64)
    sgemm_xt<<<gProj, 256>>>(x, Wq, nullptr, q, Mrows, Dm, Dm);
    sgemm_xt<<<gProj, 256>>>(x, Wk, nullptr, k, Mrows, Dm, Dm);
    sgemm_xt<<<gProj, 256>>>(x, Wv, nullptr, v, Mrows, Dm, Dm);

    dim3 gScore(Lseq / 64, Lseq / 64, Bsz * Hn);   // (32, 32, 64)
    scores_kernel<<<gScore, 256>>>(q, k, Aout);

    softmax_rows<<<Bsz * Hn * Lseq, 256>>>(Aout);

    dim3 gAV(Lseq / 64, Bsz * Hn);       // (32, 64)
    av_kernel<<<gAV, 256>>>(Aout, v, t);

    sgemm_xt<<<gProj, 256>>>(t, Wo, bo, outp, Mrows, Dm, Dm);
}

// round 2
// speedup vs baseline: 2.1506x; 2.1506x over previous
#include <cuda_runtime.h>
#include <math.h>
#include <stdint.h>

// Problem constants
#define Bsz  4
#define Lseq 2048
#define Dm   1024
#define Hn   16
#define HD   64
#define Mrows (Bsz*Lseq)   // 8192

// Scratch (device globals — no allocation allowed)
__device__ float g_q[(size_t)Mrows * Dm];
__device__ float g_k[(size_t)Mrows * Dm];
__device__ float g_v[(size_t)Mrows * Dm];
__device__ float g_t[(size_t)Mrows * Dm];   // V intermediate (A @ v)

// ---------------------------------------------------------------------------
// tf32 helpers
// ---------------------------------------------------------------------------
__device__ __forceinline__ uint32_t tf32cvt(float x) {
    uint32_t u;
    asm("cvt.rna.tf32.f32 %0, %1;" : "=r"(u) : "f"(x));
    return u;
}

__device__ __forceinline__ void mma_tf32(float (&d)[4], const uint32_t* a, const uint32_t* b) {
    asm volatile(
        "mma.sync.aligned.m16n8k8.row.col.f32.tf32.tf32.f32 "
        "{%0,%1,%2,%3}, {%4,%5,%6,%7}, {%8,%9}, {%0,%1,%2,%3};"
        : "+f"(d[0]), "+f"(d[1]), "+f"(d[2]), "+f"(d[3])
        : "r"(a[0]), "r"(a[1]), "r"(a[2]), "r"(a[3]), "r"(b[0]), "r"(b[1]));
}

// ---------------------------------------------------------------------------
// C = alpha * A[M,K] @ B[N,K]^T (+bias).  BM=128, BN=128, BK=16, 256 threads.
// Warp grid 2x4: warp tile 64x32.  attnMode: batched per (b,h) slices of q/k.
// ---------------------------------------------------------------------------
#define GBK 16
__global__ __launch_bounds__(256) void gemm_nt_tf32(
    const float* __restrict__ Ag, const float* __restrict__ Bg,
    const float* __restrict__ bias, float* __restrict__ Cg,
    int K, int lda, int ldb, int ldc, float alpha, int attnMode)
{
    __shared__ uint32_t As[128][GBK + 4];   // [m][k], 20 words/row = 80B (16B aligned)
    __shared__ uint32_t Bs[128][GBK + 4];   // [n][k]

    const int tid = threadIdx.x;
    const int m0 = blockIdx.y * 128;
    const int n0 = blockIdx.x * 128;

    const float* Ab;
    const float* Bb;
    float* Cb;
    if (attnMode) {
        const int z = blockIdx.z, b = z >> 4, h = z & 15;
        const size_t off = (size_t)b * Lseq * Dm + (size_t)h * HD;
        Ab = Ag + off;
        Bb = Bg + off;
        Cb = Cg + (size_t)z * Lseq * Lseq;
    } else {
        Ab = Ag; Bb = Bg; Cb = Cg;
    }
    Ab += (size_t)m0 * lda;
    Bb += (size_t)n0 * ldb;

    const int lr = tid >> 1;           // 0..127
    const int lc = (tid & 1) * 8;      // 0 or 8

    const int w = tid >> 5, lane = tid & 31;
    const int wm = (w >> 2) * 64;      // 0 / 64
    const int wn = (w & 3) * 32;       // 0/32/64/96
    const int g = lane >> 2, tig = lane & 3;

    float acc[4][4][4];
    #pragma unroll
    for (int i = 0; i < 4; i++)
        #pragma unroll
        for (int j = 0; j < 4; j++)
            #pragma unroll
            for (int r = 0; r < 4; r++) acc[i][j][r] = 0.f;

    float pa[8], pb[8];
    {
        const float* ap = Ab + (size_t)lr * lda + lc;
        const float* bp = Bb + (size_t)lr * ldb + lc;
        float4 a0 = *(const float4*)ap;       float4 a1 = *(const float4*)(ap + 4);
        float4 b0 = *(const float4*)bp;       float4 b1 = *(const float4*)(bp + 4);
        pa[0]=a0.x; pa[1]=a0.y; pa[2]=a0.z; pa[3]=a0.w;
        pa[4]=a1.x; pa[5]=a1.y; pa[6]=a1.z; pa[7]=a1.w;
        pb[0]=b0.x; pb[1]=b0.y; pb[2]=b0.z; pb[3]=b0.w;
        pb[4]=b1.x; pb[5]=b1.y; pb[6]=b1.z; pb[7]=b1.w;
    }
    {
        uint4 u0 = make_uint4(tf32cvt(pa[0]), tf32cvt(pa[1]), tf32cvt(pa[2]), tf32cvt(pa[3]));
        uint4 u1 = make_uint4(tf32cvt(pa[4]), tf32cvt(pa[5]), tf32cvt(pa[6]), tf32cvt(pa[7]));
        *(uint4*)&As[lr][lc]     = u0;
        *(uint4*)&As[lr][lc + 4] = u1;
        uint4 v0 = make_uint4(tf32cvt(pb[0]), tf32cvt(pb[1]), tf32cvt(pb[2]), tf32cvt(pb[3]));
        uint4 v1 = make_uint4(tf32cvt(pb[4]), tf32cvt(pb[5]), tf32cvt(pb[6]), tf32cvt(pb[7]));
        *(uint4*)&Bs[lr][lc]     = v0;
        *(uint4*)&Bs[lr][lc + 4] = v1;
    }
    __syncthreads();

    const int nk = K / GBK;
    for (int kt = 0; kt < nk; kt++) {
        if (kt + 1 < nk) {
            const float* ap = Ab + (size_t)lr * lda + (kt + 1) * GBK + lc;
            const float* bp = Bb + (size_t)lr * ldb + (kt + 1) * GBK + lc;
            float4 a0 = *(const float4*)ap;   float4 a1 = *(const float4*)(ap + 4);
            float4 b0 = *(const float4*)bp;   float4 b1 = *(const float4*)(bp + 4);
            pa[0]=a0.x; pa[1]=a0.y; pa[2]=a0.z; pa[3]=a0.w;
            pa[4]=a1.x; pa[5]=a1.y; pa[6]=a1.z; pa[7]=a1.w;
            pb[0]=b0.x; pb[1]=b0.y; pb[2]=b0.z; pb[3]=b0.w;
            pb[4]=b1.x; pb[5]=b1.y; pb[6]=b1.z; pb[7]=b1.w;
        }

        #pragma unroll
        for (int ks = 0; ks < GBK; ks += 8) {
            uint32_t af[4][4], bf[4][2];
            #pragma unroll
            for (int i = 0; i < 4; i++) {
                const int r = wm + i * 16 + g;
                af[i][0] = As[r][ks + tig];
                af[i][1] = As[r + 8][ks + tig];
                af[i][2] = As[r][ks + tig + 4];
                af[i][3] = As[r + 8][ks + tig + 4];
            }
            #pragma unroll
            for (int j = 0; j < 4; j++) {
                const int n = wn + j * 8 + g;
                bf[j][0] = Bs[n][ks + tig];
                bf[j][1] = Bs[n][ks + tig + 4];
            }
            #pragma unroll
            for (int i = 0; i < 4; i++)
                #pragma unroll
                for (int j = 0; j < 4; j++)
                    mma_tf32(acc[i][j], af[i], bf[j]);
        }
        __syncthreads();
        if (kt + 1 < nk) {
            uint4 u0 = make_uint4(tf32cvt(pa[0]), tf32cvt(pa[1]), tf32cvt(pa[2]), tf32cvt(pa[3]));
            uint4 u1 = make_uint4(tf32cvt(pa[4]), tf32cvt(pa[5]), tf32cvt(pa[6]), tf32cvt(pa[7]));
            *(uint4*)&As[lr][lc]     = u0;
            *(uint4*)&As[lr][lc + 4] = u1;
            uint4 v0 = make_uint4(tf32cvt(pb[0]), tf32cvt(pb[1]), tf32cvt(pb[2]), tf32cvt(pb[3]));
            uint4 v1 = make_uint4(tf32cvt(pb[4]), tf32cvt(pb[5]), tf32cvt(pb[6]), tf32cvt(pb[7]));
            *(uint4*)&Bs[lr][lc]     = v0;
            *(uint4*)&Bs[lr][lc + 4] = v1;
            __syncthreads();
        }
    }

    // epilogue
    #pragma unroll
    for (int i = 0; i < 4; i++) {
        #pragma unroll
        for (int j = 0; j < 4; j++) {
            const int row = m0 + wm + i * 16 + g;
            const int col = n0 + wn + j * 8 + 2 * tig;
            float b0 = 0.f, b1 = 0.f;
            if (bias) { b0 = bias[col]; b1 = bias[col + 1]; }
            float2 o0, o1;
            o0.x = alpha * acc[i][j][0] + b0;
            o0.y = alpha * acc[i][j][1] + b1;
            o1.x = alpha * acc[i][j][2] + b0;
            o1.y = alpha * acc[i][j][3] + b1;
            *(float2*)(Cb + (size_t)row * ldc + col)       = o0;
            *(float2*)(Cb + (size_t)(row + 8) * ldc + col) = o1;
        }
    }
}

// ---------------------------------------------------------------------------
// AV: Vout[b,l,h*64+d] = sum_s A[bh,l,s] * v[b,s,h*64+d]
// BM=128 (l), BN=64 (d), BK=32 (s), 256 threads, warp grid 4x2, warp tile 32x32.
// ---------------------------------------------------------------------------
__global__ __launch_bounds__(256) void av_tf32(
    const float* __restrict__ Amat, const float* __restrict__ v,
    float* __restrict__ Vout)
{
    __shared__ uint32_t As[128][36];   // [l][s] 36 words = 144B rows (16B aligned)
    __shared__ uint32_t Vs[32][72];    // [s][d] 72 words = 288B rows

    const int tid = threadIdx.x;
    const int bh = blockIdx.y;
    const int b = bh >> 4, h = bh & 15;
    const int l0 = blockIdx.x * 128;

    const float* Ab = Amat + ((size_t)bh * Lseq + l0) * Lseq;
    const float* vb = v + (size_t)b * Lseq * Dm + (size_t)h * HD;

    const int lr = tid >> 1;               // 0..127 (l)
    const int lc = (tid & 1) * 16;         // 0/16   (s)
    const int vr = tid >> 3;               // 0..31  (s)
    const int vc = (tid & 7) * 8;          // 0..56  (d)

    const int w = tid >> 5, lane = tid & 31;
    const int wm = (w >> 1) * 32;          // 0/32/64/96
    const int wn = (w & 1) * 32;           // 0/32
    const int g = lane >> 2, tig = lane & 3;

    float acc[2][4][4];
    #pragma unroll
    for (int i = 0; i < 2; i++)
        #pragma unroll
        for (int j = 0; j < 4; j++)
            #pragma unroll
            for (int r = 0; r < 4; r++) acc[i][j][r] = 0.f;

    float pa[16], pv[8];
    {
        const float* ap = Ab + (size_t)lr * Lseq + lc;
        #pragma unroll
        for (int q = 0; q < 4; q++) {
            float4 x = *(const float4*)(ap + q * 4);
            pa[q*4+0]=x.x; pa[q*4+1]=x.y; pa[q*4+2]=x.z; pa[q*4+3]=x.w;
        }
        const float* vp = vb + (size_t)vr * Dm + vc;
        #pragma unroll
        for (int q = 0; q < 2; q++) {
            float4 x = *(const float4*)(vp + q * 4);
            pv[q*4+0]=x.x; pv[q*4+1]=x.y; pv[q*4+2]=x.z; pv[q*4+3]=x.w;
        }
    }
    #pragma unroll
    for (int q = 0; q < 4; q++)
        *(uint4*)&As[lr][lc + q*4] =
            make_uint4(tf32cvt(pa[q*4+0]), tf32cvt(pa[q*4+1]), tf32cvt(pa[q*4+2]), tf32cvt(pa[q*4+3]));
    #pragma unroll
    for (int q = 0; q < 2; q++)
        *(uint4*)&Vs[vr][vc + q*4] =
            make_uint4(tf32cvt(pv[q*4+0]), tf32cvt(pv[q*4+1]), tf32cvt(pv[q*4+2]), tf32cvt(pv[q*4+3]));
    __syncthreads();

    const int nk = Lseq / 32;   // 64
    for (int kt = 0; kt < nk; kt++) {
        if (kt + 1 < nk) {
            const float* ap = Ab + (size_t)lr * Lseq + (kt + 1) * 32 + lc;
            #pragma unroll
            for (int q = 0; q < 4; q++) {
                float4 x = *(const float4*)(ap + q * 4);
                pa[q*4+0]=x.x; pa[q*4+1]=x.y; pa[q*4+2]=x.z; pa[q*4+3]=x.w;
            }
            const float* vp = vb + (size_t)((kt + 1) * 32 + vr) * Dm + vc;
            #pragma unroll
            for (int q = 0; q < 2; q++) {
                float4 x = *(const float4*)(vp + q * 4);
                pv[q*4+0]=x.x; pv[q*4+1]=x.y; pv[q*4+2]=x.z; pv[q*4+3]=x.w;
            }
        }

        #pragma unroll
        for (int ks = 0; ks < 32; ks += 8) {
            uint32_t af[2][4], bf[4][2];
            #pragma unroll
            for (int i = 0; i < 2; i++) {
                const int r = wm + i * 16 + g;
                af[i][0] = As[r][ks + tig];
                af[i][1] = As[r + 8][ks + tig];
                af[i][2] = As[r][ks + tig + 4];
                af[i][3] = As[r + 8][ks + tig + 4];
            }
            #pragma unroll
            for (int j = 0; j < 4; j++) {
                const int n = wn + j * 8 + g;
                bf[j][0] = Vs[ks + tig][n];
                bf[j][1] = Vs[ks + tig + 4][n];
            }
            #pragma unroll
            for (int i = 0; i < 2; i++)
                #pragma unroll
                for (int j = 0; j < 4; j++)
                    mma_tf32(acc[i][j], af[i], bf[j]);
        }
        __syncthreads();
        if (kt + 1 < nk) {
            #pragma unroll
            for (int q = 0; q < 4; q++)
                *(uint4*)&As[lr][lc + q*4] =
                    make_uint4(tf32cvt(pa[q*4+0]), tf32cvt(pa[q*4+1]), tf32cvt(pa[q*4+2]), tf32cvt(pa[q*4+3]));
            #pragma unroll
            for (int q = 0; q < 2; q++)
                *(uint4*)&Vs[vr][vc + q*4] =
                    make_uint4(tf32cvt(pv[q*4+0]), tf32cvt(pv[q*4+1]), tf32cvt(pv[q*4+2]), tf32cvt(pv[q*4+3]));
            __syncthreads();
        }
    }

    #pragma unroll
    for (int i = 0; i < 2; i++) {
        #pragma unroll
        for (int j = 0; j < 4; j++) {
            const int row = l0 + wm + i * 16 + g;
            const int col = wn + j * 8 + 2 * tig;
            float* o = Vout + (size_t)(b * Lseq + row) * Dm + (size_t)h * HD + col;
            *(float2*)o = make_float2(acc[i][j][0], acc[i][j][1]);
            *(float2*)(o + 8 * Dm) = make_float2(acc[i][j][2], acc[i][j][3]);
        }
    }
}

// ---------------------------------------------------------------------------
// softmax over last dim (L=2048), in place. One block (256 thr) per row.
// ---------------------------------------------------------------------------
__global__ __launch_bounds__(256) void softmax_rows(float* __restrict__ Aio)
{
    __shared__ float red[8];
    __shared__ float bcast;

    float* rp = Aio + (size_t)blockIdx.x * Lseq;
    const int tid  = threadIdx.x;
    const int lane = tid & 31;
    const int wid  = tid >> 5;

    float4 v0 = *(float4*)(rp + tid * 8);
    float4 v1 = *(float4*)(rp + tid * 8 + 4);

    float m = fmaxf(fmaxf(fmaxf(v0.x, v0.y), fmaxf(v0.z, v0.w)),
                    fmaxf(fmaxf(v1.x, v1.y), fmaxf(v1.z, v1.w)));
    #pragma unroll
    for (int o = 16; o; o >>= 1) m = fmaxf(m, __shfl_xor_sync(0xffffffffu, m, o));
    if (lane == 0) red[wid] = m;
    __syncthreads();
    if (tid < 32) {
        float t = (lane < 8) ? red[lane] : -INFINITY;
        #pragma unroll
        for (int o = 4; o; o >>= 1) t = fmaxf(t, __shfl_xor_sync(0xffffffffu, t, o));
        if (lane == 0) bcast = t;
    }
    __syncthreads();
    m = bcast;
    __syncthreads();

    v0.x = __expf(v0.x - m); v0.y = __expf(v0.y - m);
    v0.z = __expf(v0.z - m); v0.w = __expf(v0.w - m);
    v1.x = __expf(v1.x - m); v1.y = __expf(v1.y - m);
    v1.z = __expf(v1.z - m); v1.w = __expf(v1.w - m);

    float s = (v0.x + v0.y) + (v0.z + v0.w) + (v1.x + v1.y) + (v1.z + v1.w);
    #pragma unroll
    for (int o = 16; o; o >>= 1) s += __shfl_xor_sync(0xffffffffu, s, o);
    if (lane == 0) red[wid] = s;
    __syncthreads();
    if (tid < 32) {
        float t = (lane < 8) ? red[lane] : 0.f;
        #pragma unroll
        for (int o = 4; o; o >>= 1) t += __shfl_xor_sync(0xffffffffu, t, o);
        if (lane == 0) bcast = t;
    }
    __syncthreads();
    const float inv = 1.0f / bcast;

    v0.x *= inv; v0.y *= inv; v0.z *= inv; v0.w *= inv;
    v1.x *= inv; v1.y *= inv; v1.z *= inv; v1.w *= inv;
    *(float4*)(rp + tid * 8)     = v0;
    *(float4*)(rp + tid * 8 + 4) = v1;
}

// ---------------------------------------------------------------------------
extern "C" void kernel_launch(void* const* d_in, const int* in_sizes, int n_in,
                              void* d_out, int out_size)
{
    const float* x  = (const float*)d_in[0];
    // d_in[1] = key_indices (unused by the reference)
    const float* Wq = (const float*)d_in[2];
    const float* Wk = (const float*)d_in[3];
    const float* Wv = (const float*)d_in[4];
    const float* Wo = (const float*)d_in[5];
    const float* bo = (const float*)d_in[6];

    float* outp = (float*)d_out;
    float* Aout = outp + (size_t)Mrows * Dm;   // A follows out in the output buffer

    float *q, *k, *v, *t;
    cudaGetSymbolAddress((void**)&q, g_q);
    cudaGetSymbolAddress((void**)&k, g_k);
    cudaGetSymbolAddress((void**)&v, g_v);
    cudaGetSymbolAddress((void**)&t, g_t);

    // QKV projections: C[8192,1024] = x @ W^T
    dim3 gProj(Dm / 128, Mrows / 128, 1);    // (8, 64)
    gemm_nt_tf32<<<gProj, 256>>>(x, Wq, nullptr, q, Dm, Dm, Dm, Dm, 1.0f, 0);
    gemm_nt_tf32<<<gProj, 256>>>(x, Wk, nullptr, k, Dm, Dm, Dm, Dm, 1.0f, 0);
    gemm_nt_tf32<<<gProj, 256>>>(x, Wv, nullptr, v, Dm, Dm, Dm, Dm, 1.0f, 0);

    // scores = 0.125 * q @ k^T per (b,h)
    dim3 gScore(Lseq / 128, Lseq / 128, Bsz * Hn);   // (16, 16, 64)
    gemm_nt_tf32<<<gScore, 256>>>(q, k, nullptr, Aout, HD, Dm, Dm, Lseq, 0.125f, 1);

    softmax_rows<<<Bsz * Hn * Lseq, 256>>>(Aout);

    dim3 gAV(Lseq / 128, Bsz * Hn);          // (16, 64)
    av_tf32<<<gAV, 256>>>(Aout, v, t);

    // output projection with bias
    gemm_nt_tf32<<<gProj, 256>>>(t, Wo, bo, outp, Dm, Dm, Dm, Dm, 1.0f, 0);
}

// round 3
// speedup vs baseline: 2.4005x; 1.1162x over previous
#include <cuda_runtime.h>
#include <math.h>
#include <stdint.h>

// Problem constants
#define Bsz  4
#define Lseq 2048
#define Dm   1024
#define Hn   16
#define HD   64
#define Mrows (Bsz*Lseq)   // 8192
#define QLD  3072          // fused qkv row stride

// Scratch (device globals — no allocation allowed)
__device__ float g_qkv[(size_t)Mrows * QLD];   // q|k|v fused, 100MB
__device__ float g_t  [(size_t)Mrows * Dm];    // A@v intermediate
__device__ float g_xr [(size_t)Mrows * Dm];    // tf32-rounded x
__device__ float g_wr [(size_t)3 * Dm * Dm];   // tf32-rounded [Wq;Wk;Wv]
__device__ float g_wor[(size_t)Dm * Dm];       // tf32-rounded Wo

// ---------------------------------------------------------------------------
__device__ __forceinline__ uint32_t tf32cvt(float x) {
    uint32_t u; asm("cvt.rna.tf32.f32 %0, %1;" : "=r"(u) : "f"(x)); return u;
}
__device__ __forceinline__ float tf32r(float x) { return __uint_as_float(tf32cvt(x)); }

__device__ __forceinline__ void mma_tf32(float (&d)[4], const uint32_t* a, const uint32_t* b) {
    asm volatile(
        "mma.sync.aligned.m16n8k8.row.col.f32.tf32.tf32.f32 "
        "{%0,%1,%2,%3}, {%4,%5,%6,%7}, {%8,%9}, {%0,%1,%2,%3};"
        : "+f"(d[0]), "+f"(d[1]), "+f"(d[2]), "+f"(d[3])
        : "r"(a[0]), "r"(a[1]), "r"(a[2]), "r"(a[3]), "r"(b[0]), "r"(b[1]));
}

__device__ __forceinline__ void cpa16(void* dst, const void* src) {
    uint32_t d = (uint32_t)__cvta_generic_to_shared(dst);
    asm volatile("cp.async.ca.shared.global [%0], [%1], 16;" :: "r"(d), "l"(src));
}
__device__ __forceinline__ void cpa_commit() { asm volatile("cp.async.commit_group;"); }
__device__ __forceinline__ void cpa_wait1()  { asm volatile("cp.async.wait_group 1;"); }
__device__ __forceinline__ void cpa_wait0()  { asm volatile("cp.async.wait_group 0;"); }

// ---------------------------------------------------------------------------
// elementwise rna-tf32 rounding pass (float4 vectorized)
// ---------------------------------------------------------------------------
__global__ void round_tf32_k(const float* __restrict__ s, float* __restrict__ d, int n4)
{
    int i = blockIdx.x * blockDim.x + threadIdx.x;
    if (i < n4) {
        float4 v = ((const float4*)s)[i];
        v.x = tf32r(v.x); v.y = tf32r(v.y); v.z = tf32r(v.z); v.w = tf32r(v.w);
        ((float4*)d)[i] = v;
    }
}

// ---------------------------------------------------------------------------
// C = alpha * A[M,K] @ B[N,K]^T (+bias). BM=BN=128, BK=16, 256 thr,
// warps 2x4 (64x32 warp tile). 2-stage cp.async pipeline. Inputs already
// rna-tf32-rounded (raw-bit mma is exact).
// attnMode: per-z (b,h) slices inside the fused qkv buffer.
// ---------------------------------------------------------------------------
__global__ __launch_bounds__(256) void gemm_nt_ca(
    const float* __restrict__ Ag, const float* __restrict__ Bg,
    const float* __restrict__ bias, float* __restrict__ Cg,
    int K, int lda, int ldb, int ldc, float alpha, int attnMode, int roundC)
{
    __shared__ float As[2][128][20];
    __shared__ float Bs[2][128][20];

    const int tid = threadIdx.x;
    const int m0 = blockIdx.y * 128;
    const int n0 = blockIdx.x * 128;

    const float *Ab, *Bb; float* Cb;
    if (attnMode) {
        const int z = blockIdx.z, b = z >> 4, h = z & 15;
        const size_t off = (size_t)b * Lseq * QLD + (size_t)h * HD;
        Ab = Ag + off; Bb = Bg + off;
        Cb = Cg + (size_t)z * Lseq * Lseq;
    } else { Ab = Ag; Bb = Bg; Cb = Cg; }
    Ab += (size_t)m0 * lda;
    Bb += (size_t)n0 * ldb;

    const int Lr = tid >> 1, Lc = (tid & 1) * 8;
    const int w = tid >> 5, lane = tid & 31;
    const int wm = (w >> 2) * 64, wn = (w & 3) * 32;
    const int g = lane >> 2, tig = lane & 3;

    float acc[4][4][4];
    #pragma unroll
    for (int i = 0; i < 4; i++)
        #pragma unroll
        for (int j = 0; j < 4; j++)
            #pragma unroll
            for (int r = 0; r < 4; r++) acc[i][j][r] = 0.f;

    const int nk = K / 16;
    // prologue: stages 0 and 1 (nk >= 4 always here)
    {
        const float* ap = Ab + (size_t)Lr * lda + Lc;
        const float* bp = Bb + (size_t)Lr * ldb + Lc;
        cpa16(&As[0][Lr][Lc], ap);     cpa16(&As[0][Lr][Lc + 4], ap + 4);
        cpa16(&Bs[0][Lr][Lc], bp);     cpa16(&Bs[0][Lr][Lc + 4], bp + 4);
        cpa_commit();
        cpa16(&As[1][Lr][Lc], ap + 16); cpa16(&As[1][Lr][Lc + 4], ap + 20);
        cpa16(&Bs[1][Lr][Lc], bp + 16); cpa16(&Bs[1][Lr][Lc + 4], bp + 20);
        cpa_commit();
    }

    for (int kt = 0; kt < nk; kt++) {
        if (kt + 1 < nk) cpa_wait1(); else cpa_wait0();
        __syncthreads();
        const int st = kt & 1;

        #pragma unroll
        for (int ks = 0; ks < 16; ks += 8) {
            uint32_t af[4][4], bf[4][2];
            #pragma unroll
            for (int i = 0; i < 4; i++) {
                const int r = wm + i * 16 + g;
                af[i][0] = __float_as_uint(As[st][r][ks + tig]);
                af[i][1] = __float_as_uint(As[st][r + 8][ks + tig]);
                af[i][2] = __float_as_uint(As[st][r][ks + tig + 4]);
                af[i][3] = __float_as_uint(As[st][r + 8][ks + tig + 4]);
            }
            #pragma unroll
            for (int j = 0; j < 4; j++) {
                const int n = wn + j * 8 + g;
                bf[j][0] = __float_as_uint(Bs[st][n][ks + tig]);
                bf[j][1] = __float_as_uint(Bs[st][n][ks + tig + 4]);
            }
            #pragma unroll
            for (int i = 0; i < 4; i++)
                #pragma unroll
                for (int j = 0; j < 4; j++)
                    mma_tf32(acc[i][j], af[i], bf[j]);
        }
        __syncthreads();

        if (kt + 2 < nk) {
            const float* ap = Ab + (size_t)Lr * lda + (kt + 2) * 16 + Lc;
            const float* bp = Bb + (size_t)Lr * ldb + (kt + 2) * 16 + Lc;
            cpa16(&As[st][Lr][Lc], ap); cpa16(&As[st][Lr][Lc + 4], ap + 4);
            cpa16(&Bs[st][Lr][Lc], bp); cpa16(&Bs[st][Lr][Lc + 4], bp + 4);
            cpa_commit();
        }
    }

    #pragma unroll
    for (int i = 0; i < 4; i++) {
        #pragma unroll
        for (int j = 0; j < 4; j++) {
            const int row = m0 + wm + i * 16 + g;
            const int col = n0 + wn + j * 8 + 2 * tig;
            float b0 = 0.f, b1 = 0.f;
            if (bias) { b0 = bias[col]; b1 = bias[col + 1]; }
            float2 o0 = make_float2(alpha * acc[i][j][0] + b0, alpha * acc[i][j][1] + b1);
            float2 o1 = make_float2(alpha * acc[i][j][2] + b0, alpha * acc[i][j][3] + b1);
            if (roundC) {
                o0.x = tf32r(o0.x); o0.y = tf32r(o0.y);
                o1.x = tf32r(o1.x); o1.y = tf32r(o1.y);
            }
            *(float2*)(Cb + (size_t)row * ldc + col)       = o0;
            *(float2*)(Cb + (size_t)(row + 8) * ldc + col) = o1;
        }
    }
}

// ---------------------------------------------------------------------------
// AV: t[b,l,h*64+d] = sum_s A[bh,l,s] * v[b,s,h*64+d]
// BM=128(l), BN=64(d), BK=16(s), warps 4x2 (32x32 warp tile), cp.async 2-stage.
// A already tf32-rounded by softmax; v rounded by proj epilogue.
// Output t rounded for the final projection.
// ---------------------------------------------------------------------------
__global__ __launch_bounds__(256) void av_ca(
    const float* __restrict__ Amat, const float* __restrict__ v,
    float* __restrict__ Vout)
{
    __shared__ float As[2][128][20];   // [l][s]
    __shared__ float Vs[2][16][72];    // [s][d] (stride 72 -> conflict-free frag loads)

    const int tid = threadIdx.x;
    const int bh = blockIdx.y, b = bh >> 4, h = bh & 15;
    const int l0 = blockIdx.x * 128;

    const float* Ab = Amat + ((size_t)bh * Lseq + l0) * Lseq;
    const float* vb = v + (size_t)b * Lseq * QLD + (size_t)h * HD;

    const int Lr = tid >> 1, Lc = (tid & 1) * 8;     // A loader
    const int vr = tid >> 4, vc = (tid & 15) * 4;    // V loader (16 rows x 64 cols)

    const int w = tid >> 5, lane = tid & 31;
    const int wm = (w >> 1) * 32, wn = (w & 1) * 32;
    const int g = lane >> 2, tig = lane & 3;

    float acc[2][4][4];
    #pragma unroll
    for (int i = 0; i < 2; i++)
        #pragma unroll
        for (int j = 0; j < 4; j++)
            #pragma unroll
            for (int r = 0; r < 4; r++) acc[i][j][r] = 0.f;

    const int nk = Lseq / 16;   // 128
    {
        const float* ap = Ab + (size_t)Lr * Lseq + Lc;
        cpa16(&As[0][Lr][Lc], ap); cpa16(&As[0][Lr][Lc + 4], ap + 4);
        cpa16(&Vs[0][vr][vc], vb + (size_t)vr * QLD + vc);
        cpa_commit();
        cpa16(&As[1][Lr][Lc], ap + 16); cpa16(&As[1][Lr][Lc + 4], ap + 20);
        cpa16(&Vs[1][vr][vc], vb + (size_t)(16 + vr) * QLD + vc);
        cpa_commit();
    }

    for (int kt = 0; kt < nk; kt++) {
        if (kt + 1 < nk) cpa_wait1(); else cpa_wait0();
        __syncthreads();
        const int st = kt & 1;

        #pragma unroll
        for (int ks = 0; ks < 16; ks += 8) {
            uint32_t af[2][4], bf[4][2];
            #pragma unroll
            for (int i = 0; i < 2; i++) {
                const int r = wm + i * 16 + g;
                af[i][0] = __float_as_uint(As[st][r][ks + tig]);
                af[i][1] = __float_as_uint(As[st][r + 8][ks + tig]);
                af[i][2] = __float_as_uint(As[st][r][ks + tig + 4]);
                af[i][3] = __float_as_uint(As[st][r + 8][ks + tig + 4]);
            }
            #pragma unroll
            for (int j = 0; j < 4; j++) {
                const int n = wn + j * 8 + g;
                bf[j][0] = __float_as_uint(Vs[st][ks + tig][n]);
                bf[j][1] = __float_as_uint(Vs[st][ks + tig + 4][n]);
            }
            #pragma unroll
            for (int i = 0; i < 2; i++)
                #pragma unroll
                for (int j = 0; j < 4; j++)
                    mma_tf32(acc[i][j], af[i], bf[j]);
        }
        __syncthreads();

        if (kt + 2 < nk) {
            const float* ap = Ab + (size_t)Lr * Lseq + (kt + 2) * 16 + Lc;
            cpa16(&As[st][Lr][Lc], ap); cpa16(&As[st][Lr][Lc + 4], ap + 4);
            cpa16(&Vs[st][vr][vc], vb + (size_t)((kt + 2) * 16 + vr) * QLD + vc);
            cpa_commit();
        }
    }

    #pragma unroll
    for (int i = 0; i < 2; i++) {
        #pragma unroll
        for (int j = 0; j < 4; j++) {
            const int row = l0 + wm + i * 16 + g;
            const int col = wn + j * 8 + 2 * tig;
            float* o = Vout + (size_t)(b * Lseq + row) * Dm + (size_t)h * HD + col;
            *(float2*)o = make_float2(tf32r(acc[i][j][0]), tf32r(acc[i][j][1]));
            *(float2*)(o + 8 * Dm) = make_float2(tf32r(acc[i][j][2]), tf32r(acc[i][j][3]));
        }
    }
}

// ---------------------------------------------------------------------------
// softmax over last dim (L=2048), in place, tf32-rounded output.
// ---------------------------------------------------------------------------
__global__ __launch_bounds__(256) void softmax_rows(float* __restrict__ Aio)
{
    __shared__ float red[8];
    __shared__ float bcast;

    float* rp = Aio + (size_t)blockIdx.x * Lseq;
    const int tid  = threadIdx.x;
    const int lane = tid & 31;
    const int wid  = tid >> 5;

    float4 v0 = *(float4*)(rp + tid * 8);
    float4 v1 = *(float4*)(rp + tid * 8 + 4);

    float m = fmaxf(fmaxf(fmaxf(v0.x, v0.y), fmaxf(v0.z, v0.w)),
                    fmaxf(fmaxf(v1.x, v1.y), fmaxf(v1.z, v1.w)));
    #pragma unroll
    for (int o = 16; o; o >>= 1) m = fmaxf(m, __shfl_xor_sync(0xffffffffu, m, o));
    if (lane == 0) red[wid] = m;
    __syncthreads();
    if (tid < 32) {
        float t = (lane < 8) ? red[lane] : -INFINITY;
        #pragma unroll
        for (int o = 4; o; o >>= 1) t = fmaxf(t, __shfl_xor_sync(0xffffffffu, t, o));
        if (lane == 0) bcast = t;
    }
    __syncthreads();
    m = bcast;
    __syncthreads();

    v0.x = __expf(v0.x - m); v0.y = __expf(v0.y - m);
    v0.z = __expf(v0.z - m); v0.w = __expf(v0.w - m);
    v1.x = __expf(v1.x - m); v1.y = __expf(v1.y - m);
    v1.z = __expf(v1.z - m); v1.w = __expf(v1.w - m);

    float s = (v0.x + v0.y) + (v0.z + v0.w) + (v1.x + v1.y) + (v1.z + v1.w);
    #pragma unroll
    for (int o = 16; o; o >>= 1) s += __shfl_xor_sync(0xffffffffu, s, o);
    if (lane == 0) red[wid] = s;
    __syncthreads();
    if (tid < 32) {
        float t = (lane < 8) ? red[lane] : 0.f;
        #pragma unroll
        for (int o = 4; o; o >>= 1) t += __shfl_xor_sync(0xffffffffu, t, o);
        if (lane == 0) bcast = t;
    }
    __syncthreads();
    const float inv = 1.0f / bcast;

    v0.x = tf32r(v0.x * inv); v0.y = tf32r(v0.y * inv);
    v0.z = tf32r(v0.z * inv); v0.w = tf32r(v0.w * inv);
    v1.x = tf32r(v1.x * inv); v1.y = tf32r(v1.y * inv);
    v1.z = tf32r(v1.z * inv); v1.w = tf32r(v1.w * inv);
    *(float4*)(rp + tid * 8)     = v0;
    *(float4*)(rp + tid * 8 + 4) = v1;
}

// ---------------------------------------------------------------------------
extern "C" void kernel_launch(void* const* d_in, const int* in_sizes, int n_in,
                              void* d_out, int out_size)
{
    const float* x  = (const float*)d_in[0];
    // d_in[1] = key_indices (unused by the reference)
    const float* Wq = (const float*)d_in[2];
    const float* Wk = (const float*)d_in[3];
    const float* Wv = (const float*)d_in[4];
    const float* Wo = (const float*)d_in[5];
    const float* bo = (const float*)d_in[6];

    float* outp = (float*)d_out;
    float* Aout = outp + (size_t)Mrows * Dm;   // A follows out in the output buffer

    float *qkv, *t, *xr, *wr, *wor;
    cudaGetSymbolAddress((void**)&qkv, g_qkv);
    cudaGetSymbolAddress((void**)&t,   g_t);
    cudaGetSymbolAddress((void**)&xr,  g_xr);
    cudaGetSymbolAddress((void**)&wr,  g_wr);
    cudaGetSymbolAddress((void**)&wor, g_wor);

    // rna-tf32 pre-rounding (makes raw-bit tf32 mma exact)
    const int nx4 = Mrows * Dm / 4;          // 2M
    const int nw4 = Dm * Dm / 4;             // 256K
    round_tf32_k<<<(nx4 + 255) / 256, 256>>>(x,  xr,             nx4);
    round_tf32_k<<<(nw4 + 255) / 256, 256>>>(Wq, wr,             nw4);
    round_tf32_k<<<(nw4 + 255) / 256, 256>>>(Wk, wr + Dm * Dm,   nw4);
    round_tf32_k<<<(nw4 + 255) / 256, 256>>>(Wv, wr + 2 * Dm * Dm, nw4);
    round_tf32_k<<<(nw4 + 255) / 256, 256>>>(Wo, wor,            nw4);

    // fused QKV projection: qkv[8192,3072] = xr @ [Wq;Wk;Wv]^T (tf32-rounded out)
    dim3 gQKV(QLD / 128, Mrows / 128);       // (24, 64)
    gemm_nt_ca<<<gQKV, 256>>>(xr, wr, nullptr, qkv, Dm, Dm, Dm, QLD, 1.0f, 0, 1);

    // scores = 0.125 * q @ k^T per (b,h)
    dim3 gS(Lseq / 128, Lseq / 128, Bsz * Hn);   // (16, 16, 64)
    gemm_nt_ca<<<gS, 256>>>(qkv, qkv + Dm, nullptr, Aout, HD, QLD, QLD, Lseq, 0.125f, 1, 0);

    softmax_rows<<<Bsz * Hn * Lseq, 256>>>(Aout);

    dim3 gAV(Lseq / 128, Bsz * Hn);          // (16, 64)
    av_ca<<<gAV, 256>>>(Aout, qkv + 2 * Dm, t);

    // output projection with bias (fp32 output, no rounding)
    dim3 gO(Dm / 128, Mrows / 128);          // (8, 64)
    gemm_nt_ca<<<gO, 256>>>(t, wor, bo, outp, Dm, Dm, Dm, Dm, 1.0f, 0, 0);
}

// round 5
// speedup vs baseline: 3.5146x; 1.4641x over previous
#include <cuda_runtime.h>
#include <cuda_fp16.h>
#include <math.h>
#include <stdint.h>

// Problem constants
#define Bsz  4
#define Lseq 2048
#define Dm   1024
#define Hn   16
#define HD   64
#define Mrows (Bsz*Lseq)   // 8192
#define QLD  3072          // fused qkv row stride (halves)

// Scratch (device globals — no allocation allowed)
__device__ __half g_xh  [(size_t)Mrows * Dm];           // fp16 x
__device__ __half g_wh  [(size_t)3 * Dm * Dm];          // fp16 [Wq;Wk;Wv]
__device__ __half g_woh [(size_t)Dm * Dm];              // fp16 Wo
__device__ __half g_qkvh[(size_t)Mrows * QLD];          // fp16 q|k|v fused
__device__ __half g_th  [(size_t)Mrows * Dm];           // fp16 A@v result
__device__ __half g_vth [(size_t)Bsz * Hn * HD * Lseq]; // fp16 v transposed [z][d][s]
__device__ __half g_Ah  [(size_t)Bsz * Hn * Lseq * Lseq]; // fp16 copy of A

// ---------------------------------------------------------------------------
__device__ __forceinline__ void cpa16(uint32_t daddr, const void* src) {
    asm volatile("cp.async.ca.shared.global [%0], [%1], 16;" :: "r"(daddr), "l"(src));
}
__device__ __forceinline__ void cpa_commit() { asm volatile("cp.async.commit_group;"); }
__device__ __forceinline__ uint32_t smem_u32(const void* p) {
    return (uint32_t)__cvta_generic_to_shared(p);
}
__device__ __forceinline__ void ldsm4(uint32_t* r, uint32_t a) {
    asm volatile("ldmatrix.sync.aligned.m8n8.x4.shared.b16 {%0,%1,%2,%3}, [%4];"
                 : "=r"(r[0]), "=r"(r[1]), "=r"(r[2]), "=r"(r[3]) : "r"(a));
}
__device__ __forceinline__ void mmaf16(float* d, const uint32_t* a, uint32_t b0, uint32_t b1) {
    asm volatile(
        "mma.sync.aligned.m16n8k16.row.col.f32.f16.f16.f32 "
        "{%0,%1,%2,%3}, {%4,%5,%6,%7}, {%8,%9}, {%0,%1,%2,%3};"
        : "+f"(d[0]), "+f"(d[1]), "+f"(d[2]), "+f"(d[3])
        : "r"(a[0]), "r"(a[1]), "r"(a[2]), "r"(a[3]), "r"(b0), "r"(b1));
}

// ---------------------------------------------------------------------------
// fp16 NT GEMM: C = alpha * A[M,K] @ B[N,K]^T (+bias)
// BM=128, BN in {128,64}, BK=32 halves (64B rows, chunk-XOR swizzle).
// 256 threads, warps 2(m) x 4(n), warp tile 64 x BN/4, m16n8k16.
// MODE 0: proj -> fp16 C. MODE 1: scores (z-sliced qkv) -> fp32 C.
// MODE 2: AV (z-batched A, vT) -> fp16 C scattered per head.
// MODE 3: out proj -> fp32 C + bias.
// ---------------------------------------------------------------------------
template<int BN, int MODE>
__global__ __launch_bounds__(256) void hgemm(
    const __half* __restrict__ Ag, const __half* __restrict__ Bg,
    const float* __restrict__ bias, void* __restrict__ Cg,
    int K, int lda, int ldb, int ldc, float alpha)
{
    constexpr int WN = BN / 4;        // warp n extent
    constexpr int NG = WN / 16;       // B x4-ldmatrix groups per ks
    constexpr int NJ = WN / 8;        // n8 frags per warp
    constexpr int ABYTES = 128 * 64;  // 8192
    constexpr int BBYTES = BN * 64;
    constexpr int STAGE = ABYTES + BBYTES;

    extern __shared__ char smem[];
    const uint32_t sb = smem_u32(smem);

    const int tid = threadIdx.x;
    const int w = tid >> 5, lane = tid & 31;
    const int wm = (w >> 2) * 64, wn = (w & 3) * WN;
    const int g = lane >> 2, tig = lane & 3;
    const int l15 = lane & 15, lh = lane >> 4;
    const int sel = (l15 >> 1) & 3;

    const int m0 = blockIdx.y * 128;
    const int n0 = blockIdx.x * BN;
    const int z  = blockIdx.z;

    const __half* Ab;
    const __half* Bb;
    float* Cf = nullptr;
    __half* Ch = nullptr;

    if (MODE == 1) {
        const size_t off = (size_t)(z >> 4) * Lseq * QLD + (size_t)(z & 15) * HD;
        Ab = Ag + off + (size_t)m0 * lda;
        Bb = Bg + off + (size_t)n0 * ldb;
        Cf = (float*)Cg + (size_t)z * Lseq * Lseq + (size_t)m0 * ldc + n0;
    } else if (MODE == 2) {
        Ab = Ag + (size_t)z * Lseq * Lseq + (size_t)m0 * lda;
        Bb = Bg + (size_t)z * HD * Lseq + (size_t)n0 * ldb;
        Ch = (__half*)Cg + ((size_t)(z >> 4) * Lseq + m0) * Dm + (size_t)(z & 15) * HD + n0;
    } else {
        Ab = Ag + (size_t)m0 * lda;
        Bb = Bg + (size_t)n0 * ldb;
        if (MODE == 0) Ch = (__half*)Cg + (size_t)m0 * ldc + n0;
        else           Cf = (float*)Cg + (size_t)m0 * ldc + n0;
    }

    float acc[4][NJ][4];
    #pragma unroll
    for (int i = 0; i < 4; i++)
        #pragma unroll
        for (int j = 0; j < NJ; j++)
            #pragma unroll
            for (int r = 0; r < 4; r++) acc[i][j][r] = 0.f;

    const int nk = K / 32;

    auto ldA = [&](int kt, int st) {
        const uint32_t base = sb + st * STAGE;
        const int r = tid >> 1;
        const int c0 = (tid & 1) * 2;
        const __half* src = Ab + (size_t)r * lda + kt * 32;
        #pragma unroll
        for (int c = 0; c < 2; c++) {
            const int cc = c0 + c;
            cpa16(base + r * 64 + ((cc ^ ((r >> 1) & 3)) * 16), src + cc * 8);
        }
    };
    auto ldB = [&](int kt, int st) {
        const uint32_t base = sb + st * STAGE + ABYTES;
        if (BN == 128) {
            const int r = tid >> 1;
            const int c0 = (tid & 1) * 2;
            const __half* src = Bb + (size_t)r * ldb + kt * 32;
            #pragma unroll
            for (int c = 0; c < 2; c++) {
                const int cc = c0 + c;
                cpa16(base + r * 64 + ((cc ^ ((r >> 1) & 3)) * 16), src + cc * 8);
            }
        } else {
            const int r = tid >> 2;
            const int cc = tid & 3;
            const __half* src = Bb + (size_t)r * ldb + kt * 32;
            cpa16(base + r * 64 + ((cc ^ ((r >> 1) & 3)) * 16), src + cc * 8);
        }
    };

    // prologue
    int issued = 0;
    #pragma unroll
    for (int t = 0; t < 3; t++)
        if (t < nk) { ldA(t, t); ldB(t, t); cpa_commit(); issued++; }

    for (int kt = 0; kt < nk; kt++) {
        const int pend = issued - (kt + 1);
        if (pend <= 0)      asm volatile("cp.async.wait_group 0;");
        else if (pend == 1) asm volatile("cp.async.wait_group 1;");
        else                asm volatile("cp.async.wait_group 2;");
        __syncthreads();

        const int st = kt % 3;
        const uint32_t aB = sb + st * STAGE;
        const uint32_t bB = aB + ABYTES;

        #pragma unroll
        for (int ks = 0; ks < 2; ks++) {
            const uint32_t chunk = ((uint32_t)(lh + 2 * ks) ^ (uint32_t)sel) * 16;
            uint32_t af[4][4];
            #pragma unroll
            for (int i = 0; i < 4; i++)
                ldsm4(af[i], aB + (wm + 16 * i + l15) * 64 + chunk);
            uint32_t bf[NG][4];
            #pragma unroll
            for (int jg = 0; jg < NG; jg++)
                ldsm4(bf[jg], bB + (wn + 16 * jg + l15) * 64 + chunk);
            #pragma unroll
            for (int i = 0; i < 4; i++)
                #pragma unroll
                for (int jg = 0; jg < NG; jg++) {
                    mmaf16(acc[i][2 * jg + 0], af[i], bf[jg][0], bf[jg][2]);
                    mmaf16(acc[i][2 * jg + 1], af[i], bf[jg][1], bf[jg][3]);
                }
        }
        __syncthreads();

        if (issued < nk) {
            ldA(issued, issued % 3); ldB(issued, issued % 3);
            cpa_commit();
            issued++;
        }
    }

    // epilogue
    #pragma unroll
    for (int i = 0; i < 4; i++) {
        const int row = wm + 16 * i + g;
        #pragma unroll
        for (int j = 0; j < NJ; j++) {
            const int col = wn + 8 * j + 2 * tig;
            float a0 = acc[i][j][0], a1 = acc[i][j][1];
            float a2 = acc[i][j][2], a3 = acc[i][j][3];
            if (MODE == 1) { a0 *= alpha; a1 *= alpha; a2 *= alpha; a3 *= alpha; }
            if (MODE == 3) {
                const float b0 = bias[n0 + col], b1 = bias[n0 + col + 1];
                a0 += b0; a1 += b1; a2 += b0; a3 += b1;
            }
            if (MODE == 0 || MODE == 2) {
                *(__half2*)(Ch + (size_t)row * ldc + col) =
                    __halves2half2(__float2half_rn(a0), __float2half_rn(a1));
                *(__half2*)(Ch + (size_t)(row + 8) * ldc + col) =
                    __halves2half2(__float2half_rn(a2), __float2half_rn(a3));
            } else {
                *(float2*)(Cf + (size_t)row * ldc + col)       = make_float2(a0, a1);
                *(float2*)(Cf + (size_t)(row + 8) * ldc + col) = make_float2(a2, a3);
            }
        }
    }
}

// ---------------------------------------------------------------------------
// fp32 -> fp16 conversion (8 elems per thread)
// ---------------------------------------------------------------------------
__global__ void cvt_h(const float* __restrict__ s, __half* __restrict__ d, int n8)
{
    int i = blockIdx.x * blockDim.x + threadIdx.x;
    if (i < n8) {
        float4 v0 = ((const float4*)s)[2 * i];
        float4 v1 = ((const float4*)s)[2 * i + 1];
        __half2* o = (__half2*)d + 4 * (size_t)i;
        o[0] = __halves2half2(__float2half_rn(v0.x), __float2half_rn(v0.y));
        o[1] = __halves2half2(__float2half_rn(v0.z), __float2half_rn(v0.w));
        o[2] = __halves2half2(__float2half_rn(v1.x), __float2half_rn(v1.y));
        o[3] = __halves2half2(__float2half_rn(v1.z), __float2half_rn(v1.w));
    }
}

// ---------------------------------------------------------------------------
// transpose v (fp16, within fused qkv) to vT[z][d][s]
// ---------------------------------------------------------------------------
__global__ __launch_bounds__(256) void transpose_v(
    const __half* __restrict__ qkvh, __half* __restrict__ vt)
{
    __shared__ __half tile[32][33];
    const int z = blockIdx.z, b = z >> 4, h = z & 15;
    const int s0 = blockIdx.x * 32;
    const int d0 = blockIdx.y * 32;
    const int tx = threadIdx.x, ty = threadIdx.y;

    const __half* src = qkvh + (size_t)b * Lseq * QLD + 2 * Dm + (size_t)h * HD;
    #pragma unroll
    for (int i = 0; i < 32; i += 8)
        tile[ty + i][tx] = src[(size_t)(s0 + ty + i) * QLD + d0 + tx];
    __syncthreads();
    __half* dst = vt + (size_t)z * HD * Lseq;
    #pragma unroll
    for (int i = 0; i < 32; i += 8)
        dst[(size_t)(d0 + ty + i) * Lseq + s0 + tx] = tile[tx][ty + i];
}

// ---------------------------------------------------------------------------
// softmax over last dim (L=2048), fp32 in/out + fp16 copy.
// ---------------------------------------------------------------------------
__global__ __launch_bounds__(256) void softmax_rows(
    float* __restrict__ Aio, __half* __restrict__ Ah)
{
    __shared__ float red[8];
    __shared__ float bcast;

    float* rp = Aio + (size_t)blockIdx.x * Lseq;
    __half* hp = Ah + (size_t)blockIdx.x * Lseq;
    const int tid  = threadIdx.x;
    const int lane = tid & 31;
    const int wid  = tid >> 5;

    float4 v0 = *(float4*)(rp + tid * 8);
    float4 v1 = *(float4*)(rp + tid * 8 + 4);

    float m = fmaxf(fmaxf(fmaxf(v0.x, v0.y), fmaxf(v0.z, v0.w)),
                    fmaxf(fmaxf(v1.x, v1.y), fmaxf(v1.z, v1.w)));
    #pragma unroll
    for (int o = 16; o; o >>= 1) m = fmaxf(m, __shfl_xor_sync(0xffffffffu, m, o));
    if (lane == 0) red[wid] = m;
    __syncthreads();
    if (tid < 32) {
        float t = (lane < 8) ? red[lane] : -INFINITY;
        #pragma unroll
        for (int o = 4; o; o >>= 1) t = fmaxf(t, __shfl_xor_sync(0xffffffffu, t, o));
        if (lane == 0) bcast = t;
    }
    __syncthreads();
    m = bcast;
    __syncthreads();

    v0.x = __expf(v0.x - m); v0.y = __expf(v0.y - m);
    v0.z = __expf(v0.z - m); v0.w = __expf(v0.w - m);
    v1.x = __expf(v1.x - m); v1.y = __expf(v1.y - m);
    v1.z = __expf(v1.z - m); v1.w = __expf(v1.w - m);

    float s = (v0.x + v0.y) + (v0.z + v0.w) + (v1.x + v1.y) + (v1.z + v1.w);
    #pragma unroll
    for (int o = 16; o; o >>= 1) s += __shfl_xor_sync(0xffffffffu, s, o);
    if (lane == 0) red[wid] = s;
    __syncthreads();
    if (tid < 32) {
        float t = (lane < 8) ? red[lane] : 0.f;
        #pragma unroll
        for (int o = 4; o; o >>= 1) t += __shfl_xor_sync(0xffffffffu, t, o);
        if (lane == 0) bcast = t;
    }
    __syncthreads();
    const float inv = 1.0f / bcast;

    v0.x *= inv; v0.y *= inv; v0.z *= inv; v0.w *= inv;
    v1.x *= inv; v1.y *= inv; v1.z *= inv; v1.w *= inv;
    *(float4*)(rp + tid * 8)     = v0;
    *(float4*)(rp + tid * 8 + 4) = v1;

    __half2* h2 = (__half2*)(hp + tid * 8);
    h2[0] = __halves2half2(__float2half_rn(v0.x), __float2half_rn(v0.y));
    h2[1] = __halves2half2(__float2half_rn(v0.z), __float2half_rn(v0.w));
    h2[2] = __halves2half2(__float2half_rn(v1.x), __float2half_rn(v1.y));
    h2[3] = __halves2half2(__float2half_rn(v1.z), __float2half_rn(v1.w));
}

// ---------------------------------------------------------------------------
extern "C" void kernel_launch(void* const* d_in, const int* in_sizes, int n_in,
                              void* d_out, int out_size)
{
    const float* x  = (const float*)d_in[0];
    // d_in[1] = key_indices (unused by the reference)
    const float* Wq = (const float*)d_in[2];
    const float* Wk = (const float*)d_in[3];
    const float* Wv = (const float*)d_in[4];
    const float* Wo = (const float*)d_in[5];
    const float* bo = (const float*)d_in[6];

    float* outp = (float*)d_out;
    float* Aout = outp + (size_t)Mrows * Dm;   // A follows out in the output buffer

    __half *xh, *wh, *woh, *qkvh, *th, *vth, *Ah;
    cudaGetSymbolAddress((void**)&xh,   g_xh);
    cudaGetSymbolAddress((void**)&wh,   g_wh);
    cudaGetSymbolAddress((void**)&woh,  g_woh);
    cudaGetSymbolAddress((void**)&qkvh, g_qkvh);
    cudaGetSymbolAddress((void**)&th,   g_th);
    cudaGetSymbolAddress((void**)&vth,  g_vth);
    cudaGetSymbolAddress((void**)&Ah,   g_Ah);

    const int SM128 = 3 * (8192 + 8192);   // 49152
    const int SM64  = 3 * (8192 + 4096);   // 36864

    // fp16 conversions
    const int nx8 = Mrows * Dm / 8;
    const int nw8 = Dm * Dm / 8;
    cvt_h<<<(nx8 + 255) / 256, 256>>>(x,  xh,               nx8);
    cvt_h<<<(nw8 + 255) / 256, 256>>>(Wq, wh,               nw8);
    cvt_h<<<(nw8 + 255) / 256, 256>>>(Wk, wh + Dm * Dm,     nw8);
    cvt_h<<<(nw8 + 255) / 256, 256>>>(Wv, wh + 2 * Dm * Dm, nw8);
    cvt_h<<<(nw8 + 255) / 256, 256>>>(Wo, woh,              nw8);

    // fused QKV projection: qkvh[8192,3072] = xh @ wh^T
    {
        dim3 g(QLD / 128, Mrows / 128, 1);   // (24, 64)
        hgemm<128, 0><<<g, 256, SM128>>>(xh, wh, nullptr, qkvh,
                                         Dm, Dm, Dm, QLD, 1.0f);
    }
    // scores = 0.125 * q @ k^T per (b,h), fp32 output to Aout
    {
        dim3 g(Lseq / 128, Lseq / 128, Bsz * Hn);   // (16, 16, 64)
        hgemm<128, 1><<<g, 256, SM128>>>(qkvh, qkvh + Dm, nullptr, Aout,
                                         HD, QLD, QLD, Lseq, 0.125f);
    }

    softmax_rows<<<Bsz * Hn * Lseq, 256>>>(Aout, Ah);

    // transpose v -> vT[z][d][s]
    {
        dim3 g(Lseq / 32, HD / 32, Bsz * Hn);
        transpose_v<<<g, dim3(32, 8)>>>(qkvh, vth);
    }
    // AV: th = Ah @ vT^T per z
    {
        dim3 g(1, Lseq / 128, Bsz * Hn);   // (1, 16, 64)
        hgemm<64, 2><<<g, 256, SM64>>>(Ah, vth, nullptr, th,
                                       Lseq, Lseq, Lseq, Dm, 1.0f);
    }
    // output projection with bias
    {
        dim3 g(Dm / 128, Mrows / 128, 1);   // (8, 64)
        hgemm<128, 3><<<g, 256, SM128>>>(th, woh, bo, outp,
                                         Dm, Dm, Dm, Dm, 1.0f);
    }
}

// round 6
// speedup vs baseline: 3.9930x; 1.1361x over previous
#include <cuda_runtime.h>
#include <cuda_fp16.h>
#include <math.h>
#include <stdint.h>

// Problem constants
#define Bsz  4
#define Lseq 2048
#define Dm   1024
#define Hn   16
#define HD   64
#define Mrows (Bsz*Lseq)   // 8192
#define QLD  3072          // fused qkv row stride (halves)

// Scratch (device globals — no allocation allowed)
__device__ __half g_xh  [(size_t)Mrows * Dm];
__device__ __half g_wh  [(size_t)3 * Dm * Dm];
__device__ __half g_woh [(size_t)Dm * Dm];
__device__ __half g_qkvh[(size_t)Mrows * QLD];
__device__ __half g_th  [(size_t)Mrows * Dm];
__device__ __half g_vth [(size_t)Bsz * Hn * HD * Lseq];
__device__ __half g_Ah  [(size_t)Bsz * Hn * Lseq * Lseq];

// ---------------------------------------------------------------------------
__device__ __forceinline__ void cpa16(uint32_t daddr, const void* src) {
    asm volatile("cp.async.ca.shared.global [%0], [%1], 16;" :: "r"(daddr), "l"(src));
}
__device__ __forceinline__ void cpa_commit() { asm volatile("cp.async.commit_group;"); }
__device__ __forceinline__ uint32_t smem_u32(const void* p) {
    return (uint32_t)__cvta_generic_to_shared(p);
}
__device__ __forceinline__ void ldsm4(uint32_t* r, uint32_t a) {
    asm volatile("ldmatrix.sync.aligned.m8n8.x4.shared.b16 {%0,%1,%2,%3}, [%4];"
                 : "=r"(r[0]), "=r"(r[1]), "=r"(r[2]), "=r"(r[3]) : "r"(a));
}
__device__ __forceinline__ void mmaf16(float* d, const uint32_t* a, uint32_t b0, uint32_t b1) {
    asm volatile(
        "mma.sync.aligned.m16n8k16.row.col.f32.f16.f16.f32 "
        "{%0,%1,%2,%3}, {%4,%5,%6,%7}, {%8,%9}, {%0,%1,%2,%3};"
        : "+f"(d[0]), "+f"(d[1]), "+f"(d[2]), "+f"(d[3])
        : "r"(a[0]), "r"(a[1]), "r"(a[2]), "r"(a[3]), "r"(b0), "r"(b1));
}

// ---------------------------------------------------------------------------
// fp16 NT GEMM: C = alpha * A[M,K] @ B[N,K]^T (+bias)
// MODE 0: proj -> fp16 C.  MODE 2: AV (z-batched A, vT) -> fp16 C per head.
// MODE 3: out proj -> fp32 C + bias.
// ---------------------------------------------------------------------------
template<int BN, int MODE>
__global__ __launch_bounds__(256) void hgemm(
    const __half* __restrict__ Ag, const __half* __restrict__ Bg,
    const float* __restrict__ bias, void* __restrict__ Cg,
    int K, int lda, int ldb, int ldc, float alpha)
{
    constexpr int WN = BN / 4;
    constexpr int NG = WN / 16;
    constexpr int NJ = WN / 8;
    constexpr int ABYTES = 128 * 64;
    constexpr int BBYTES = BN * 64;
    constexpr int STAGE = ABYTES + BBYTES;

    extern __shared__ char smem[];
    const uint32_t sb = smem_u32(smem);

    const int tid = threadIdx.x;
    const int w = tid >> 5, lane = tid & 31;
    const int wm = (w >> 2) * 64, wn = (w & 3) * WN;
    const int g = lane >> 2, tig = lane & 3;
    const int l15 = lane & 15, lh = lane >> 4;
    const int sel = (l15 >> 1) & 3;

    const int m0 = blockIdx.y * 128;
    const int n0 = blockIdx.x * BN;
    const int z  = blockIdx.z;

    const __half* Ab;
    const __half* Bb;
    float* Cf = nullptr;
    __half* Ch = nullptr;

    if (MODE == 2) {
        Ab = Ag + (size_t)z * Lseq * Lseq + (size_t)m0 * lda;
        Bb = Bg + (size_t)z * HD * Lseq + (size_t)n0 * ldb;
        Ch = (__half*)Cg + ((size_t)(z >> 4) * Lseq + m0) * Dm + (size_t)(z & 15) * HD + n0;
    } else {
        Ab = Ag + (size_t)m0 * lda;
        Bb = Bg + (size_t)n0 * ldb;
        if (MODE == 0) Ch = (__half*)Cg + (size_t)m0 * ldc + n0;
        else           Cf = (float*)Cg + (size_t)m0 * ldc + n0;
    }

    float acc[4][NJ][4];
    #pragma unroll
    for (int i = 0; i < 4; i++)
        #pragma unroll
        for (int j = 0; j < NJ; j++)
            #pragma unroll
            for (int r = 0; r < 4; r++) acc[i][j][r] = 0.f;

    const int nk = K / 32;

    auto ldA = [&](int kt, int st) {
        const uint32_t base = sb + st * STAGE;
        const int r = tid >> 1;
        const int c0 = (tid & 1) * 2;
        const __half* src = Ab + (size_t)r * lda + kt * 32;
        #pragma unroll
        for (int c = 0; c < 2; c++) {
            const int cc = c0 + c;
            cpa16(base + r * 64 + ((cc ^ ((r >> 1) & 3)) * 16), src + cc * 8);
        }
    };
    auto ldB = [&](int kt, int st) {
        const uint32_t base = sb + st * STAGE + ABYTES;
        if (BN == 128) {
            const int r = tid >> 1;
            const int c0 = (tid & 1) * 2;
            const __half* src = Bb + (size_t)r * ldb + kt * 32;
            #pragma unroll
            for (int c = 0; c < 2; c++) {
                const int cc = c0 + c;
                cpa16(base + r * 64 + ((cc ^ ((r >> 1) & 3)) * 16), src + cc * 8);
            }
        } else {
            const int r = tid >> 2;
            const int cc = tid & 3;
            const __half* src = Bb + (size_t)r * ldb + kt * 32;
            cpa16(base + r * 64 + ((cc ^ ((r >> 1) & 3)) * 16), src + cc * 8);
        }
    };

    int issued = 0;
    #pragma unroll
    for (int t = 0; t < 3; t++)
        if (t < nk) { ldA(t, t); ldB(t, t); cpa_commit(); issued++; }

    for (int kt = 0; kt < nk; kt++) {
        const int pend = issued - (kt + 1);
        if (pend <= 0)      asm volatile("cp.async.wait_group 0;");
        else if (pend == 1) asm volatile("cp.async.wait_group 1;");
        else                asm volatile("cp.async.wait_group 2;");
        __syncthreads();

        const int st = kt % 3;
        const uint32_t aB = sb + st * STAGE;
        const uint32_t bB = aB + ABYTES;

        #pragma unroll
        for (int ks = 0; ks < 2; ks++) {
            const uint32_t chunk = ((uint32_t)(lh + 2 * ks) ^ (uint32_t)sel) * 16;
            uint32_t af[4][4];
            #pragma unroll
            for (int i = 0; i < 4; i++)
                ldsm4(af[i], aB + (wm + 16 * i + l15) * 64 + chunk);
            uint32_t bf[NG][4];
            #pragma unroll
            for (int jg = 0; jg < NG; jg++)
                ldsm4(bf[jg], bB + (wn + 16 * jg + l15) * 64 + chunk);
            #pragma unroll
            for (int i = 0; i < 4; i++)
                #pragma unroll
                for (int jg = 0; jg < NG; jg++) {
                    mmaf16(acc[i][2 * jg + 0], af[i], bf[jg][0], bf[jg][2]);
                    mmaf16(acc[i][2 * jg + 1], af[i], bf[jg][1], bf[jg][3]);
                }
        }
        __syncthreads();

        if (issued < nk) {
            ldA(issued, issued % 3); ldB(issued, issued % 3);
            cpa_commit();
            issued++;
        }
    }

    #pragma unroll
    for (int i = 0; i < 4; i++) {
        const int row = wm + 16 * i + g;
        #pragma unroll
        for (int j = 0; j < NJ; j++) {
            const int col = wn + 8 * j + 2 * tig;
            float a0 = acc[i][j][0], a1 = acc[i][j][1];
            float a2 = acc[i][j][2], a3 = acc[i][j][3];
            if (MODE == 3) {
                const float b0 = bias[n0 + col], b1 = bias[n0 + col + 1];
                a0 += b0; a1 += b1; a2 += b0; a3 += b1;
            }
            if (MODE == 0 || MODE == 2) {
                *(__half2*)(Ch + (size_t)row * ldc + col) =
                    __halves2half2(__float2half_rn(a0), __float2half_rn(a1));
                *(__half2*)(Ch + (size_t)(row + 8) * ldc + col) =
                    __halves2half2(__float2half_rn(a2), __float2half_rn(a3));
            } else {
                *(float2*)(Cf + (size_t)row * ldc + col)       = make_float2(a0, a1);
                *(float2*)(Cf + (size_t)(row + 8) * ldc + col) = make_float2(a2, a3);
            }
        }
    }
}

// ---------------------------------------------------------------------------
// Fused scores + softmax: one CTA = 16 query rows of one (b,h).
// Computes 16x2048 score strip (fp32 in smem), softmaxes, writes fp32 A + fp16 Ah.
// smem: Q 2KB | K 2x32KB | scores 16x2056 fp32 (128.5KB)  => ~199KB
// ---------------------------------------------------------------------------
#define ASM_Q 0
#define ASM_K 2048
#define ASM_S (2048 + 65536)
#define ASM_TOTAL (ASM_S + 16 * 2056 * 4)
#define SSTRIDE 2056

__global__ __launch_bounds__(256) void attn_fused(
    const __half* __restrict__ qkvh, float* __restrict__ Aout, __half* __restrict__ Ah)
{
    extern __shared__ char smem[];
    const uint32_t sb = smem_u32(smem);
    float* scoresS = (float*)(smem + ASM_S);

    const int tid = threadIdx.x;
    const int w = tid >> 5, lane = tid & 31;
    const int l15 = lane & 15, lh = lane >> 4, sel = (l15 >> 1) & 3;
    const int g = lane >> 2, tig = lane & 3;

    const int l0 = blockIdx.x * 16;
    const int z  = blockIdx.y;
    const int b = z >> 4, h = z & 15;

    const __half* qb = qkvh + ((size_t)b * Lseq + l0) * QLD + h * HD;
    const __half* kb = qkvh + (size_t)b * Lseq * QLD + Dm + h * HD;

    // Q load (group 0, with K panel 0)
    if (tid < 128) {
        const int row = tid >> 3, col8 = tid & 7;
        const int p = col8 >> 2, c = col8 & 3;
        cpa16(sb + ASM_Q + p * 1024 + row * 64 + ((c ^ ((row >> 1) & 3)) * 16),
              qb + (size_t)row * QLD + col8 * 8);
    }
    auto ldK = [&](int nt, int buf) {
        const int col8 = tid & 7;
        const int p = col8 >> 2, c = col8 & 3;
        #pragma unroll
        for (int i = 0; i < 8; i++) {
            const int row = (tid >> 3) + i * 32;
            cpa16(sb + ASM_K + buf * 32768 + p * 16384 + row * 64 +
                      ((c ^ ((row >> 1) & 3)) * 16),
                  kb + (size_t)(nt * 256 + row) * QLD + col8 * 8);
        }
    };
    ldK(0, 0); cpa_commit();
    ldK(1, 1); cpa_commit();

    asm volatile("cp.async.wait_group 1;");
    __syncthreads();

    // Q fragments (held for whole kernel)
    uint32_t af[4][4];
    #pragma unroll
    for (int kk = 0; kk < 4; kk++) {
        const int kh = kk >> 1, ks = kk & 1;
        ldsm4(af[kk], sb + ASM_Q + kh * 1024 + l15 * 64 + (((lh + 2 * ks) ^ sel) * 16));
    }

    for (int nt = 0; nt < 8; nt++) {
        if (nt > 0) {
            if (nt < 7) asm volatile("cp.async.wait_group 1;");
            else        asm volatile("cp.async.wait_group 0;");
            __syncthreads();
        }
        const uint32_t Kb = sb + ASM_K + (nt & 1) * 32768;

        float acc[4][4];
        #pragma unroll
        for (int j = 0; j < 4; j++)
            #pragma unroll
            for (int r = 0; r < 4; r++) acc[j][r] = 0.f;

        #pragma unroll
        for (int kk = 0; kk < 4; kk++) {
            const int kh = kk >> 1, ks = kk & 1;
            const uint32_t chunk = (((uint32_t)lh + 2 * ks) ^ (uint32_t)sel) * 16;
            uint32_t bf0[4], bf1[4];
            ldsm4(bf0, Kb + kh * 16384 + (w * 32 + l15) * 64 + chunk);
            ldsm4(bf1, Kb + kh * 16384 + (w * 32 + 16 + l15) * 64 + chunk);
            mmaf16(acc[0], af[kk], bf0[0], bf0[2]);
            mmaf16(acc[1], af[kk], bf0[1], bf0[3]);
            mmaf16(acc[2], af[kk], bf1[0], bf1[2]);
            mmaf16(acc[3], af[kk], bf1[1], bf1[3]);
        }

        #pragma unroll
        for (int j = 0; j < 4; j++) {
            const int col = nt * 256 + w * 32 + j * 8 + 2 * tig;
            *(float2*)&scoresS[g * SSTRIDE + col] =
                make_float2(acc[j][0] * 0.125f, acc[j][1] * 0.125f);
            *(float2*)&scoresS[(g + 8) * SSTRIDE + col] =
                make_float2(acc[j][2] * 0.125f, acc[j][3] * 0.125f);
        }
        __syncthreads();
        if (nt + 2 < 8) { ldK(nt + 2, nt & 1); cpa_commit(); }
    }

    // softmax: warp w handles rows w and w+8
    #pragma unroll
    for (int rr = 0; rr < 2; rr++) {
        const int r = w + rr * 8;
        const float* rp = &scoresS[r * SSTRIDE];
        float vals[64];
        float m = -INFINITY;
        #pragma unroll
        for (int c = 0; c < 16; c++) {
            float4 vv = *(const float4*)&rp[lane * 4 + c * 128];
            vals[4 * c + 0] = vv.x; vals[4 * c + 1] = vv.y;
            vals[4 * c + 2] = vv.z; vals[4 * c + 3] = vv.w;
            m = fmaxf(m, fmaxf(fmaxf(vv.x, vv.y), fmaxf(vv.z, vv.w)));
        }
        #pragma unroll
        for (int o = 16; o; o >>= 1) m = fmaxf(m, __shfl_xor_sync(0xffffffffu, m, o));

        float s = 0.f;
        #pragma unroll
        for (int i = 0; i < 64; i++) { vals[i] = __expf(vals[i] - m); s += vals[i]; }
        #pragma unroll
        for (int o = 16; o; o >>= 1) s += __shfl_xor_sync(0xffffffffu, s, o);
        const float inv = 1.0f / s;

        float* op = Aout + ((size_t)z * Lseq + l0 + r) * Lseq;
        __half* hp = Ah + ((size_t)z * Lseq + l0 + r) * Lseq;
        #pragma unroll
        for (int c = 0; c < 16; c++) {
            float4 o;
            o.x = vals[4 * c + 0] * inv; o.y = vals[4 * c + 1] * inv;
            o.z = vals[4 * c + 2] * inv; o.w = vals[4 * c + 3] * inv;
            *(float4*)&op[lane * 4 + c * 128] = o;
            __half2 h0 = __halves2half2(__float2half_rn(o.x), __float2half_rn(o.y));
            __half2 h1 = __halves2half2(__float2half_rn(o.z), __float2half_rn(o.w));
            *(__half2*)&hp[lane * 4 + c * 128]     = h0;
            *(__half2*)&hp[lane * 4 + c * 128 + 2] = h1;
        }
    }
}

// ---------------------------------------------------------------------------
__global__ void cvt_h(const float* __restrict__ s, __half* __restrict__ d, int n8)
{
    int i = blockIdx.x * blockDim.x + threadIdx.x;
    if (i < n8) {
        float4 v0 = ((const float4*)s)[2 * i];
        float4 v1 = ((const float4*)s)[2 * i + 1];
        __half2* o = (__half2*)d + 4 * (size_t)i;
        o[0] = __halves2half2(__float2half_rn(v0.x), __float2half_rn(v0.y));
        o[1] = __halves2half2(__float2half_rn(v0.z), __float2half_rn(v0.w));
        o[2] = __halves2half2(__float2half_rn(v1.x), __float2half_rn(v1.y));
        o[3] = __halves2half2(__float2half_rn(v1.z), __float2half_rn(v1.w));
    }
}

// ---------------------------------------------------------------------------
__global__ __launch_bounds__(256) void transpose_v(
    const __half* __restrict__ qkvh, __half* __restrict__ vt)
{
    __shared__ __half tile[32][33];
    const int z = blockIdx.z, b = z >> 4, h = z & 15;
    const int s0 = blockIdx.x * 32;
    const int d0 = blockIdx.y * 32;
    const int tx = threadIdx.x, ty = threadIdx.y;

    const __half* src = qkvh + (size_t)b * Lseq * QLD + 2 * Dm + (size_t)h * HD;
    #pragma unroll
    for (int i = 0; i < 32; i += 8)
        tile[ty + i][tx] = src[(size_t)(s0 + ty + i) * QLD + d0 + tx];
    __syncthreads();
    __half* dst = vt + (size_t)z * HD * Lseq;
    #pragma unroll
    for (int i = 0; i < 32; i += 8)
        dst[(size_t)(d0 + ty + i) * Lseq + s0 + tx] = tile[tx][ty + i];
}

// ---------------------------------------------------------------------------
extern "C" void kernel_launch(void* const* d_in, const int* in_sizes, int n_in,
                              void* d_out, int out_size)
{
    const float* x  = (const float*)d_in[0];
    // d_in[1] = key_indices (unused by the reference)
    const float* Wq = (const float*)d_in[2];
    const float* Wk = (const float*)d_in[3];
    const float* Wv = (const float*)d_in[4];
    const float* Wo = (const float*)d_in[5];
    const float* bo = (const float*)d_in[6];

    float* outp = (float*)d_out;
    float* Aout = outp + (size_t)Mrows * Dm;

    __half *xh, *wh, *woh, *qkvh, *th, *vth, *Ah;
    cudaGetSymbolAddress((void**)&xh,   g_xh);
    cudaGetSymbolAddress((void**)&wh,   g_wh);
    cudaGetSymbolAddress((void**)&woh,  g_woh);
    cudaGetSymbolAddress((void**)&qkvh, g_qkvh);
    cudaGetSymbolAddress((void**)&th,   g_th);
    cudaGetSymbolAddress((void**)&vth,  g_vth);
    cudaGetSymbolAddress((void**)&Ah,   g_Ah);

    const int SM128 = 3 * (8192 + 8192);
    const int SM64  = 3 * (8192 + 4096);
    cudaFuncSetAttribute(hgemm<128, 0>, cudaFuncAttributeMaxDynamicSharedMemorySize, SM128);
    cudaFuncSetAttribute(hgemm<128, 3>, cudaFuncAttributeMaxDynamicSharedMemorySize, SM128);
    cudaFuncSetAttribute(hgemm<64, 2>,  cudaFuncAttributeMaxDynamicSharedMemorySize, SM64);
    cudaFuncSetAttribute(attn_fused,    cudaFuncAttributeMaxDynamicSharedMemorySize, ASM_TOTAL);

    // fp16 conversions
    const int nx8 = Mrows * Dm / 8;
    const int nw8 = Dm * Dm / 8;
    cvt_h<<<(nx8 + 255) / 256, 256>>>(x,  xh,               nx8);
    cvt_h<<<(nw8 + 255) / 256, 256>>>(Wq, wh,               nw8);
    cvt_h<<<(nw8 + 255) / 256, 256>>>(Wk, wh + Dm * Dm,     nw8);
    cvt_h<<<(nw8 + 255) / 256, 256>>>(Wv, wh + 2 * Dm * Dm, nw8);
    cvt_h<<<(nw8 + 255) / 256, 256>>>(Wo, woh,              nw8);

    // fused QKV projection
    {
        dim3 g(QLD / 128, Mrows / 128, 1);
        hgemm<128, 0><<<g, 256, SM128>>>(xh, wh, nullptr, qkvh,
                                         Dm, Dm, Dm, QLD, 1.0f);
    }
    // fused scores + softmax -> fp32 A + fp16 Ah
    {
        dim3 g(Lseq / 16, Bsz * Hn);   // (128, 64)
        attn_fused<<<g, 256, ASM_TOTAL>>>(qkvh, Aout, Ah);
    }
    // transpose v -> vT[z][d][s]
    {
        dim3 g(Lseq / 32, HD / 32, Bsz * Hn);
        transpose_v<<<g, dim3(32, 8)>>>(qkvh, vth);
    }
    // AV
    {
        dim3 g(1, Lseq / 128, Bsz * Hn);
        hgemm<64, 2><<<g, 256, SM64>>>(Ah, vth, nullptr, th,
                                       Lseq, Lseq, Lseq, Dm, 1.0f);
    }
    // output projection with bias
    {
        dim3 g(Dm / 128, Mrows / 128, 1);
        hgemm<128, 3><<<g, 256, SM128>>>(th, woh, bo, outp,
                                         Dm, Dm, Dm, Dm, 1.0f);
    }
}